// round 17
// baseline (speedup 1.0000x reference)
#include <cuda_runtime.h>
#include <cuda_fp16.h>
#include <cstdint>
#include <math.h>

#define SEQ 512
#define NB  64
#define NH  1024
#define NG  4096

// ---------------- scratch (static device globals: allocation-free) ----------------
__device__ __half g_xh [SEQ * NB * NH];  // x in fp16 (64 MB)
__device__ __half g_wih[NG * NH];        // weights fp16 (8 MB each)
__device__ __half g_whh[NG * NH];
__device__ float  g_bias[NG];            // bias_ih + bias_hh (f32)
__device__ float  g_g0 [(size_t)SEQ * NB * NG];   // precomputed X @ W_ih^T (537 MB)
__device__ __half g_h0[3][NB * NH];      // mod-3 buffered: h0[u] lives in g_h0[u%3]
__device__ __half g_h1[3][NB * NH];      // h1[u] in g_h1[u%3]
__device__ unsigned g_cnt;               // grid barrier arrival counter
__device__ volatile unsigned g_gen;      // grid barrier generation

__global__ void k_cvt(const float* __restrict__ src, int which, int n4) {
    __half* dst = (which == 0) ? g_xh : (which == 1 ? g_wih : g_whh);
    for (int i = blockIdx.x * blockDim.x + threadIdx.x; i < n4; i += gridDim.x * blockDim.x) {
        float4 v = ((const float4*)src)[i];
        ((__half2*)dst)[2 * i]     = __floats2half2_rn(v.x, v.y);
        ((__half2*)dst)[2 * i + 1] = __floats2half2_rn(v.z, v.w);
    }
}
__global__ void k_bias(const float* __restrict__ a, const float* __restrict__ b) {
    for (int i = blockIdx.x * blockDim.x + threadIdx.x; i < NG; i += gridDim.x * blockDim.x)
        g_bias[i] = a[i] + b[i];
}
__global__ void k_init() {
    int i0 = blockIdx.x * blockDim.x + threadIdx.x;
    if (i0 == 0) { g_cnt = 0u; g_gen = 0u; }
    const __half z = __float2half(0.f);
    for (int i = i0; i < NB * NH; i += gridDim.x * blockDim.x) {
        g_h0[0][i] = z; g_h0[1][i] = z; g_h0[2][i] = z;
        g_h1[0][i] = z; g_h1[1][i] = z; g_h1[2][i] = z;
    }
}

// ---------------- PTX helpers ----------------
__device__ __forceinline__ void cp16(uint32_t dst, const void* src) {
    asm volatile("cp.async.cg.shared.global [%0], [%1], 16;\n" :: "r"(dst), "l"(src));
}
#define CP_COMMIT() asm volatile("cp.async.commit_group;\n" ::: "memory")
#define CP_WAIT(N)  asm volatile("cp.async.wait_group %0;\n" :: "n"(N) : "memory")
#define BARS(id, n) asm volatile("bar.sync %0, %1;" :: "n"(id), "n"(n) : "memory")
__device__ __forceinline__ uint32_t smem_u32(const void* p) {
    uint32_t r;
    asm("{ .reg .u64 t; cvta.to.shared.u64 t, %1; cvt.u32.u64 %0, t; }" : "=r"(r) : "l"(p));
    return r;
}
__device__ __forceinline__ void ldsm4(uint32_t& r0, uint32_t& r1, uint32_t& r2, uint32_t& r3,
                                      uint32_t addr) {
    asm volatile("ldmatrix.sync.aligned.m8n8.x4.shared.b16 {%0,%1,%2,%3}, [%4];"
                 : "=r"(r0), "=r"(r1), "=r"(r2), "=r"(r3) : "r"(addr));
}
__device__ __forceinline__ void mma16816(float* a4, const uint32_t* af, uint32_t b0, uint32_t b1) {
    asm volatile(
        "mma.sync.aligned.m16n8k16.row.col.f32.f16.f16.f32 "
        "{%0,%1,%2,%3}, {%4,%5,%6,%7}, {%8,%9}, {%0,%1,%2,%3};\n"
        : "+f"(a4[0]), "+f"(a4[1]), "+f"(a4[2]), "+f"(a4[3])
        : "r"(af[0]), "r"(af[1]), "r"(af[2]), "r"(af[3]), "r"(b0), "r"(b1));
}
__device__ __forceinline__ float fsig(float x) { return 1.f / (1.f + __expf(-x)); }
__device__ __forceinline__ float ftanh(float x) { return 1.f - 2.f / (1.f + __expf(2.f * x)); }

// =============== k_pre: G0 = X[32768,1024] @ W_ih[4096,1024]^T (f32 out) ===========
#define P_STAGE (256 * 144)
#define P_SMEM  (3 * P_STAGE)                // 110592
__global__ __launch_bounds__(256) void k_pre() {
    extern __shared__ char ps[];
    const uint32_t s0 = smem_u32(ps);
    const int tid = threadIdx.x, lane = tid & 31, wid = tid >> 5;
    const int wr = (wid >> 1) * 32, wc = (wid & 1) * 64;
    const int row0 = blockIdx.y * 128, col0 = blockIdx.x * 128;
    const int g = lane >> 2, t = lane & 3, lrow = lane & 15, lhiw = (lane >> 4) * 4;
    const int bn_row = ((lane >> 4) << 3) + (lane & 7), bn_wof = ((lane >> 3) & 1) * 4;

    auto issue = [&](int ch, int st) {
        const uint32_t aU = s0 + (uint32_t)st * P_STAGE, bU = aU + 128 * 144;
        const int kb = ch * 64;
        #pragma unroll
        for (int i = 0; i < 4; i++) {
            int id = i * 256 + tid; int m = id >> 3, q = id & 7;
            cp16(aU + (uint32_t)(m * 144 + q * 16),
                 g_xh + (size_t)(row0 + m) * NH + kb + q * 8);
        }
        #pragma unroll
        for (int i = 0; i < 4; i++) {
            int id = i * 256 + tid; int m = id >> 3, q = id & 7;
            cp16(bU + (uint32_t)(m * 144 + q * 16),
                 g_wih + (size_t)(col0 + m) * NH + kb + q * 8);
        }
        CP_COMMIT();
    };

    float acc[2][8][4];
    #pragma unroll
    for (int a = 0; a < 2; a++)
        #pragma unroll
        for (int b = 0; b < 8; b++)
            #pragma unroll
            for (int c = 0; c < 4; c++) acc[a][b][c] = 0.f;

    issue(0, 0); issue(1, 1);
    for (int c = 0; c < 16; ++c) {
        if (c < 15) { CP_WAIT(1); } else { CP_WAIT(0); }
        __syncthreads();
        if (c + 2 < 16) issue(c + 2, (c + 2) % 3);
        const uint32_t aU = s0 + (uint32_t)(c % 3) * P_STAGE, bU = aU + 128 * 144;
        #pragma unroll
        for (int ks = 0; ks < 4; ks++) {
            const int ko = ks * 8;
            uint32_t afr[2][4], bfr[4][4];
            #pragma unroll
            for (int mi = 0; mi < 2; mi++)
                ldsm4(afr[mi][0], afr[mi][1], afr[mi][2], afr[mi][3],
                      aU + (uint32_t)(((wr + mi * 16 + lrow) * 36 + ko + lhiw) * 4));
            #pragma unroll
            for (int nb = 0; nb < 4; nb++)
                ldsm4(bfr[nb][0], bfr[nb][1], bfr[nb][2], bfr[nb][3],
                      bU + (uint32_t)(((wc + nb * 16 + bn_row) * 36 + ko + bn_wof) * 4));
            #pragma unroll
            for (int mi = 0; mi < 2; mi++)
                #pragma unroll
                for (int n8 = 0; n8 < 8; n8++)
                    mma16816(acc[mi][n8], afr[mi],
                             bfr[n8 >> 1][2 * (n8 & 1)], bfr[n8 >> 1][2 * (n8 & 1) + 1]);
        }
        __syncthreads();
    }
    #pragma unroll
    for (int mi = 0; mi < 2; mi++) {
        int r0 = row0 + wr + mi * 16 + g;
        #pragma unroll
        for (int n8 = 0; n8 < 8; n8++) {
            int col = col0 + wc + n8 * 8 + 2 * t;
            *(float2*)&g_g0[(size_t)r0 * NG + col]       = make_float2(acc[mi][n8][0], acc[mi][n8][1]);
            *(float2*)&g_g0[(size_t)(r0 + 8) * NG + col] = make_float2(acc[mi][n8][2], acc[mi][n8][3]);
        }
    }
}

// =============== recurrent kernel ==================================================
// R17: DUAL-PIPELINE slot. L0 group (warps 0-5, bar 1): h0[s-1]*Whh -> h0[s]
// (critical path, 256 mma/SMSP). L1 group (warps 6-15, bar 2): t1 = s-2,
// h0[t1]*Wih + h1[t1-1]*Whh -> h1[t1] + outputs (512 mma/SMSP, all inputs >=1
// grid barrier old). Groups share ONLY the end-of-slot __syncthreads + grid
// barrier, so each group's tail hides under the other group's MMA stream.
// h-state: mod-3 buffers (writer s%3; readers (s-1,s-2,s-3)%3 all distinct).
#define L0R_STAGE 9216                       // 64 rows x 144B
#define L1R_OFF   (3 * L0R_STAGE)            // 27648
#define L1R_STAGE 18432                      // h0 64 rows + h1 64 rows
#define B_OFF     (L1R_OFF + 3 * L1R_STAGE)  // 82944
#define B_CHUNK_B (32 * 144)                 // 4608
#define SMEM_TOT  (B_OFF + 32 * B_CHUNK_B)   // 230400
#define NT 512

__global__ __launch_bounds__(NT) void k_lstm(float* __restrict__ out, int wstates) {
    extern __shared__ char dyn[];

    const int tid  = threadIdx.x;
    const int lane = tid & 31;
    const int wid  = tid >> 5;
    const int j0   = blockIdx.x * 8;

    const uint32_t smem0 = smem_u32(dyn);
    const uint32_t bRes  = smem0 + B_OFF;

    // ---- resident B (once): chunk-major, 16 Wih chunks then 16 Whh chunks ----
    {
        if (tid < 256) {
            const int n = tid >> 3, q = tid & 7;
            const int grow = (n >> 3) * NH + j0 + (n & 7);
            for (int c = 0; c < 32; c++) {
                const __half* wb = (c < 16) ? g_wih : g_whh;
                const int kk = (c * 64) & (NH - 1);
                cp16(bRes + (uint32_t)(c * B_CHUNK_B + n * 144 + q * 16),
                     wb + (size_t)grow * NH + kk + q * 8);
                CP_COMMIT();
            }
        }
        CP_WAIT(0);
        __syncthreads();
    }

    const int g = lane >> 2, t = lane & 3;
    const int lrow = lane & 15, lhiw = (lane >> 4) * 4;
    const int bn_row = ((lane >> 4) << 3) + (lane & 7);
    const int bn_wof = ((lane >> 3) & 1) * 4;
    const uint32_t bFragBase = bRes + (uint32_t)((bn_row * 36 + bn_wof) * 4);

    // ---- persistent per-thread epilogue state ----
    // L0 epilogue: tid<128 (= L0 consumer warps), b=tid>>1, 4 units (ejb0)
    const int b0r  = tid >> 1;
    const int ejb0 = (tid & 1) * 4;
    float cv0[4] = {0.f, 0.f, 0.f, 0.f};
    float bias0[4][4];
    if (tid < 128)
        #pragma unroll
        for (int q = 0; q < 4; q++)
            #pragma unroll
            for (int u = 0; u < 4; u++)
                bias0[q][u] = g_bias[q * NH + j0 + ejb0 + u];
    // L1 epilogue: tid in [192,448) (= L1 consumer warps), b=(tid-192)>>2, 2 units
    const int lt1  = tid - 192;
    const int b1r  = lt1 >> 2;
    const int ejb1 = (lt1 & 3) * 2;
    float cv1[2] = {0.f, 0.f};
    float bias1[4][2];
    if (tid >= 192 && tid < 448)
        #pragma unroll
        for (int q = 0; q < 4; q++)
            #pragma unroll
            for (int u = 0; u < 2; u++)
                bias1[q][u] = g_bias[q * NH + j0 + ejb1 + u];

    float4 rg0[4];
    auto fetch_g0 = [&](int tt) {       // tid<128 only
        const size_t base = ((size_t)tt * NB + b0r) * NG + j0 + ejb0;
        #pragma unroll
        for (int q = 0; q < 4; q++) rg0[q] = *(const float4*)&g_g0[base + q * NH];
    };
    if (tid < 128) fetch_g0(0);

    for (int s = 0; s <= SEQ + 1; ++s) {
        const bool l0on = (s < SEQ);       // t0 = s
        const bool l1on = (s >= 2);        // t1 = s - 2
        const int  t1   = s - 2;

        if (wid < 6) {
            // ================= L0 pipeline =================
            if (l0on) {
                const __half* a0 = g_h0[(s + 2) % 3];    // h0[s-1]
                const bool prod = (wid >= 4);
                const int  p    = tid & 63;
                auto issue0 = [&](int c, int st) {
                    const uint32_t sU = smem0 + (uint32_t)st * L0R_STAGE;
                    const int kb = c * 64;
                    #pragma unroll
                    for (int i = 0; i < 8; i++) {
                        int id = i * 64 + p; int m = id >> 3, q = id & 7;
                        cp16(sU + (uint32_t)(m * 144 + q * 16), a0 + m * NH + kb + q * 8);
                    }
                    CP_COMMIT();
                };
                float acc[4][4];
                #pragma unroll
                for (int a = 0; a < 4; a++)
                    #pragma unroll
                    for (int c = 0; c < 4; c++) acc[a][c] = 0.f;

                if (prod) { issue0(0, 0); issue0(1, 1); }
                for (int c = 0; c < 16; ++c) {
                    if (prod) { if (c < 15) { CP_WAIT(1); } else { CP_WAIT(0); } }
                    BARS(1, 192);
                    if (prod) {
                        if (c + 2 < 16) issue0(c + 2, (c + 2) % 3);
                    } else {
                        const uint32_t aBase = smem0 + (uint32_t)(c % 3) * L0R_STAGE;
                        const uint32_t bC = bFragBase + (uint32_t)((16 + c) * B_CHUNK_B);
                        #pragma unroll
                        for (int ks = 0; ks < 4; ks++) {
                            const int ko = ks * 8;
                            uint32_t afr[4], b0[4], b1[4];
                            ldsm4(afr[0], afr[1], afr[2], afr[3],
                                  aBase + (uint32_t)(((wid * 16 + lrow) * 36 + ko + lhiw) * 4));
                            ldsm4(b0[0], b0[1], b0[2], b0[3], bC + (uint32_t)(ko * 4));
                            ldsm4(b1[0], b1[1], b1[2], b1[3], bC + (uint32_t)(16 * 144 + ko * 4));
                            mma16816(acc[0], afr, b0[0], b0[1]);
                            mma16816(acc[1], afr, b0[2], b0[3]);
                            mma16816(acc[2], afr, b1[0], b1[1]);
                            mma16816(acc[3], afr, b1[2], b1[3]);
                        }
                    }
                }
                if (!prod) {
                    BARS(3, 128);
                    float* sG0 = (float*)dyn;            // 64 x 36 (aliases L0 ring)
                    const int r = wid * 16 + g;
                    #pragma unroll
                    for (int ni = 0; ni < 4; ni++) {
                        int cc = ni * 8 + 2 * t;
                        sG0[r * 36 + cc]           = acc[ni][0];
                        sG0[r * 36 + cc + 1]       = acc[ni][1];
                        sG0[(r + 8) * 36 + cc]     = acc[ni][2];
                        sG0[(r + 8) * 36 + cc + 1] = acc[ni][3];
                    }
                    BARS(3, 128);
                    // ---- L0 epilogue: h0[s] ----
                    __half* hwb = g_h0[s % 3];
                    const int idx = b0r * NH + j0 + ejb0;
                    float hv[4];
                    #pragma unroll
                    for (int u = 0; u < 4; u++) {
                        int uu = ejb0 + u;
                        float g0v = (u == 0) ? 0.f : 0.f;   // placeholder
                        float gq[4];
                        #pragma unroll
                        for (int q = 0; q < 4; q++) {
                            float gx = (u == 0) ? rg0[q].x : (u == 1) ? rg0[q].y
                                     : (u == 2) ? rg0[q].z : rg0[q].w;
                            gq[q] = sG0[b0r * 36 + q * 8 + uu] + bias0[q][u] + gx;
                        }
                        (void)g0v;
                        float cn = fsig(gq[1]) * cv0[u] + fsig(gq[0]) * ftanh(gq[2]);
                        cv0[u] = cn;
                        hv[u] = fsig(gq[3]) * ftanh(cn);
                    }
                    *(__half2*)&hwb[idx]     = __floats2half2_rn(hv[0], hv[1]);
                    *(__half2*)&hwb[idx + 2] = __floats2half2_rn(hv[2], hv[3]);
                    if (wstates && s == SEQ - 1) {
                        #pragma unroll
                        for (int u = 0; u < 4; u++) {
                            out[(size_t)SEQ * NB * NH + idx + u]               = hv[u]; // h_n[0]
                            out[(size_t)SEQ * NB * NH + 2 * NB * NH + idx + u] = cv0[u];
                        }
                    }
                }
            }
        } else {
            // ================= L1 pipeline (t = s-2) =================
            if (l1on) {
                const __half* a1 = g_h0[(s + 1) % 3];    // h0[s-2]
                const __half* a2 = g_h1[s % 3];          // h1[s-3]
                const bool prod = (wid >= 14);
                const int  p    = tid & 63;
                auto issue1 = [&](int c, int st) {
                    const uint32_t sU = smem0 + L1R_OFF + (uint32_t)st * L1R_STAGE;
                    const int kb = c * 64;
                    #pragma unroll
                    for (int i = 0; i < 8; i++) {
                        int id = i * 64 + p; int m = id >> 3, q = id & 7;
                        cp16(sU + (uint32_t)(m * 144 + q * 16), a1 + m * NH + kb + q * 8);
                    }
                    #pragma unroll
                    for (int i = 0; i < 8; i++) {
                        int id = i * 64 + p; int m = id >> 3, q = id & 7;
                        cp16(sU + (uint32_t)(9216 + m * 144 + q * 16), a2 + m * NH + kb + q * 8);
                    }
                    CP_COMMIT();
                };
                float acc[4][4];
                #pragma unroll
                for (int a = 0; a < 4; a++)
                    #pragma unroll
                    for (int c = 0; c < 4; c++) acc[a][c] = 0.f;

                const int cgi  = (wid - 6) >> 2;         // 0: h0*Wih, 1: h1*Whh
                const int band = (wid - 6) & 3;

                if (prod) { issue1(0, 0); issue1(1, 1); }
                for (int c = 0; c < 16; ++c) {
                    if (prod) { if (c < 15) { CP_WAIT(1); } else { CP_WAIT(0); } }
                    BARS(2, 320);
                    if (prod) {
                        if (c + 2 < 16) issue1(c + 2, (c + 2) % 3);
                    } else {
                        const uint32_t aBase = smem0 + L1R_OFF
                            + (uint32_t)(c % 3) * L1R_STAGE + (cgi ? 9216u : 0u);
                        const uint32_t bC = bFragBase
                            + (uint32_t)((cgi ? (16 + c) : c) * B_CHUNK_B);
                        #pragma unroll
                        for (int ks = 0; ks < 4; ks++) {
                            const int ko = ks * 8;
                            uint32_t afr[4], b0[4], b1[4];
                            ldsm4(afr[0], afr[1], afr[2], afr[3],
                                  aBase + (uint32_t)(((band * 16 + lrow) * 36 + ko + lhiw) * 4));
                            ldsm4(b0[0], b0[1], b0[2], b0[3], bC + (uint32_t)(ko * 4));
                            ldsm4(b1[0], b1[1], b1[2], b1[3], bC + (uint32_t)(16 * 144 + ko * 4));
                            mma16816(acc[0], afr, b0[0], b0[1]);
                            mma16816(acc[1], afr, b0[2], b0[3]);
                            mma16816(acc[2], afr, b1[0], b1[1]);
                            mma16816(acc[3], afr, b1[2], b1[3]);
                        }
                    }
                }
                if (!prod) {
                    BARS(4, 256);
                    float* sG1a = (float*)(dyn + L1R_OFF);          // 64 x 36
                    float* sG1b = (float*)(dyn + L1R_OFF + 9216);   // 64 x 36
                    float* dst = cgi ? sG1b : sG1a;
                    const int r = band * 16 + g;
                    #pragma unroll
                    for (int ni = 0; ni < 4; ni++) {
                        int cc = ni * 8 + 2 * t;
                        dst[r * 36 + cc]           = acc[ni][0];
                        dst[r * 36 + cc + 1]       = acc[ni][1];
                        dst[(r + 8) * 36 + cc]     = acc[ni][2];
                        dst[(r + 8) * 36 + cc + 1] = acc[ni][3];
                    }
                    BARS(4, 256);
                    // ---- L1 epilogue: h1[t1] + outputs[t1] ----
                    __half* hwb = g_h1[(s + 1) % 3];
                    const int idx = b1r * NH + j0 + ejb1;
                    float hv[2];
                    #pragma unroll
                    for (int u = 0; u < 2; u++) {
                        int uu = ejb1 + u;
                        float gq[4];
                        #pragma unroll
                        for (int q = 0; q < 4; q++)
                            gq[q] = sG1a[b1r * 36 + q * 8 + uu]
                                  + sG1b[b1r * 36 + q * 8 + uu] + bias1[q][u];
                        float cn = fsig(gq[1]) * cv1[u] + fsig(gq[0]) * ftanh(gq[2]);
                        cv1[u] = cn;
                        hv[u] = fsig(gq[3]) * ftanh(cn);
                    }
                    *(__half2*)&hwb[idx] = __floats2half2_rn(hv[0], hv[1]);
                    *(float2*)&out[((size_t)t1 * NB + b1r) * NH + j0 + ejb1] =
                        make_float2(hv[0], hv[1]);
                    if (wstates && t1 == SEQ - 1) {
                        #pragma unroll
                        for (int u = 0; u < 2; u++) {
                            out[(size_t)SEQ * NB * NH + NB * NH + idx + u]     = hv[u]; // h_n[1]
                            out[(size_t)SEQ * NB * NH + 3 * NB * NH + idx + u] = cv1[u];
                        }
                    }
                }
            }
        }

        // ------- grid barrier: arrive early, prefetch G0 under the wait -------
        if (s <= SEQ) {
            __syncthreads();              // both groups done; h writes done block-wide
            unsigned arr = 0u;
            if (tid == 0) {
                __threadfence();
                arr = atomicAdd(&g_cnt, 1u);     // ARRIVE (no spin yet)
            }
            if (tid < 128 && s + 1 < SEQ) fetch_g0(s + 1);   // overlaps arrivals
            if (tid == 0) {
                unsigned target = (unsigned)(s + 1);
                if (arr == 127u) {
                    g_cnt = 0u;
                    __threadfence();
                    g_gen = target;
                } else {
                    while (g_gen < target) { }
                    __threadfence();
                }
            }
            __syncthreads();
        }
    }
}

// ---------------------------------------------------------------------------------
extern "C" void kernel_launch(void* const* d_in, const int* in_sizes, int n_in,
                              void* d_out, int out_size) {
    const float* x   = (const float*)d_in[0];
    const float* wih = (const float*)d_in[1];
    const float* whh = (const float*)d_in[2];
    const float* bih = (const float*)d_in[3];
    const float* bhh = (const float*)d_in[4];
    float* out = (float*)d_out;

    const long long full = (long long)SEQ * NB * NH + 4LL * NB * NH;
    int wstates = ((long long)out_size >= full) ? 1 : 0;

    static int smem_set = 0;
    if (!smem_set) {
        cudaFuncSetAttribute(k_lstm, cudaFuncAttributeMaxDynamicSharedMemorySize, SMEM_TOT);
        cudaFuncSetAttribute(k_pre,  cudaFuncAttributeMaxDynamicSharedMemorySize, P_SMEM);
        smem_set = 1;
    }

    k_cvt<<<512, 256>>>(x, 0, SEQ * NB * NH / 4);
    k_cvt<<<256, 256>>>(wih, 1, NG * NH / 4);
    k_cvt<<<256, 256>>>(whh, 2, NG * NH / 4);
    k_bias<<<16, 256>>>(bih, bhh);
    k_init<<<128, 256>>>();

    k_pre<<<dim3(NG / 128, SEQ * NB / 128), 256, P_SMEM>>>();

    k_lstm<<<128, NT, SMEM_TOT>>>(out, wstates);
}